// round 3
// baseline (speedup 1.0000x reference)
#include <cuda_runtime.h>
#include <cuda_bf16.h>
#include <cstdint>

// Antecedent firing strengths:
//   out[s][r] = exp( sum_{d=0..7} log_mv[s, digit_d(r), d] )
// with log_mv[s][f][d] = -(x[s][d]-c[f][d])^2 / (2*sp[f][d]^2)
// and digit_d(r) = (r >> 2*(7-d)) & 3  (base-4 expansion == _fuco_frb rows).
//
// Factorization: r = hi*256 + lo, hi/lo each 4 base-4 digits (4^4 = 256):
//   out[s][r] = eA[hi] * eB[lo]
// eA covers dims 0..3, eB covers dims 4..7. Only 512 exps per sample.
// Main loop: smem broadcast + LDS.128 + FMUL + STG.128 -> pure write BW.

constexpr int IN_DIM  = 8;
constexpr int NUM_FS  = 4;
constexpr int NUM_SAM = 512;
constexpr int HALF    = 256;     // 4^4  (was wrongly 4096 in R2)
constexpr int RULES   = 65536;   // 4^8
constexpr int THREADS = 256;

__global__ __launch_bounds__(THREADS)
void antecedent_kernel(const float* __restrict__ x,      // [512, 8]
                       const float* __restrict__ center, // [4, 8]
                       const float* __restrict__ spread, // [4, 8]
                       float* __restrict__ out)          // [512, 65536]
{
    __shared__ float lm[NUM_FS * IN_DIM];            // log_mv for this sample
    __shared__ __align__(16) float eA[HALF];
    __shared__ __align__(16) float eB[HALF];

    const int s   = blockIdx.x;
    const int tid = threadIdx.x;

    // --- per-sample log membership table (32 values) ---
    if (tid < NUM_FS * IN_DIM) {
        const int f = tid / IN_DIM;
        const int d = tid % IN_DIM;
        const float xv = x[s * IN_DIM + d];
        const float c  = center[f * IN_DIM + d];
        const float sp = spread[f * IN_DIM + d];
        const float df = xv - c;
        lm[f * IN_DIM + d] = -(df * df) / (2.0f * sp * sp);
    }
    __syncthreads();

    // --- factorized half-sums over 4 digits each ---
    // index i in [0,256): digit for slot j (j=0 most significant) is
    // (i >> 2*(3-j)) & 3. hi half -> dims 0..3, lo half -> dims 4..7.
    if (tid < HALF) {
        const int i  = tid;
        const int g0 = (i >> 6) & 3;
        const int g1 = (i >> 4) & 3;
        const int g2 = (i >> 2) & 3;
        const int g3 =  i       & 3;
        const float a = lm[g0 * IN_DIM + 0] + lm[g1 * IN_DIM + 1]
                      + lm[g2 * IN_DIM + 2] + lm[g3 * IN_DIM + 3];
        const float b = lm[g0 * IN_DIM + 4] + lm[g1 * IN_DIM + 5]
                      + lm[g2 * IN_DIM + 6] + lm[g3 * IN_DIM + 7];
        eA[i] = __expf(a);
        eB[i] = __expf(b);
    }
    __syncthreads();

    // --- streaming write: out[s][hi*256 + lo] = eA[hi] * eB[lo] ---
    // Vec index i in [0, 16384): element index = 4*i,
    //   hi  = (4*i) >> 8 = i >> 6   (warp-uniform: 32-aligned within 64-blocks)
    //   lo4 = i & 63                (consecutive float4 of eB)
    float4* __restrict__ outv =
        reinterpret_cast<float4*>(out + (size_t)s * RULES);
    const float4* __restrict__ eBv = reinterpret_cast<const float4*>(eB);

    #pragma unroll 8
    for (int i = tid; i < RULES / 4; i += THREADS) {
        const float  a = eA[i >> 6];
        const float4 b = eBv[i & 63];
        float4 o;
        o.x = a * b.x;
        o.y = a * b.y;
        o.z = a * b.z;
        o.w = a * b.w;
        outv[i] = o;
    }
}

extern "C" void kernel_launch(void* const* d_in, const int* in_sizes, int n_in,
                              void* d_out, int out_size)
{
    const float* x      = (const float*)d_in[0];  // model_input [512,8]
    const float* center = (const float*)d_in[1];  // [4,8]
    const float* spread = (const float*)d_in[2];  // [4,8]
    // d_in[3] = fs_ind [65536,8] int32 — deterministic base-4 digit table,
    // decoded arithmetically in-kernel instead of gathered.
    (void)in_sizes; (void)n_in; (void)out_size;

    float* out = (float*)d_out;                   // [512, 65536] f32

    antecedent_kernel<<<NUM_SAM, THREADS>>>(x, center, spread, out);
}

// round 4
// speedup vs baseline: 1.1013x; 1.1013x over previous
#include <cuda_runtime.h>
#include <cuda_bf16.h>
#include <cstdint>

// Antecedent firing strengths:
//   out[s][r] = exp( sum_{d=0..7} log_mv[s, digit_d(r), d] )
// digit_d(r) = (r >> 2*(7-d)) & 3  (base-4 expansion == _fuco_frb rows).
//
// Factorization: r = hi*256 + lo (4 digits each, 4^4 = 256):
//   out[s][r] = eA[hi] * eB[lo]
// 512 exps per CTA; main loop is pure streaming STG.128.
//
// R4: split each sample across SLICES=4 CTAs (grid 2048) to raise occupancy
// (35% -> ~75%) and smooth wave imbalance; use __stcs (streaming) stores
// since the 134MB output exceeds L2 and is never re-read.

constexpr int IN_DIM  = 8;
constexpr int NUM_FS  = 4;
constexpr int NUM_SAM = 512;
constexpr int HALF    = 256;     // 4^4
constexpr int RULES   = 65536;   // 4^8
constexpr int THREADS = 256;
constexpr int SLICES  = 4;                       // CTAs per sample
constexpr int VECS    = RULES / 4;               // 16384 float4 per sample
constexpr int VECS_PER_SLICE = VECS / SLICES;    // 4096

__global__ __launch_bounds__(THREADS)
void antecedent_kernel(const float* __restrict__ x,      // [512, 8]
                       const float* __restrict__ center, // [4, 8]
                       const float* __restrict__ spread, // [4, 8]
                       float* __restrict__ out)          // [512, 65536]
{
    __shared__ float lm[NUM_FS * IN_DIM];
    __shared__ __align__(16) float eA[HALF];
    __shared__ __align__(16) float eB[HALF];

    const int s     = blockIdx.x >> 2;      // sample
    const int slice = blockIdx.x & 3;       // quarter of the sample's output
    const int tid   = threadIdx.x;

    // --- per-sample log membership table (32 values) ---
    if (tid < NUM_FS * IN_DIM) {
        const int f = tid / IN_DIM;
        const int d = tid % IN_DIM;
        const float xv = x[s * IN_DIM + d];
        const float c  = center[f * IN_DIM + d];
        const float sp = spread[f * IN_DIM + d];
        const float df = xv - c;
        lm[f * IN_DIM + d] = -(df * df) / (2.0f * sp * sp);
    }
    __syncthreads();

    // --- factorized half-sums over 4 digits each ---
    if (tid < HALF) {
        const int i  = tid;
        const int g0 = (i >> 6) & 3;
        const int g1 = (i >> 4) & 3;
        const int g2 = (i >> 2) & 3;
        const int g3 =  i       & 3;
        const float a = lm[g0 * IN_DIM + 0] + lm[g1 * IN_DIM + 1]
                      + lm[g2 * IN_DIM + 2] + lm[g3 * IN_DIM + 3];
        const float b = lm[g0 * IN_DIM + 4] + lm[g1 * IN_DIM + 5]
                      + lm[g2 * IN_DIM + 6] + lm[g3 * IN_DIM + 7];
        eA[i] = __expf(a);
        eB[i] = __expf(b);
    }
    __syncthreads();

    // --- streaming write of this slice ---
    // Vec index i (within sample): hi = i>>6 (warp-uniform), lo4 = i&63.
    float4* __restrict__ outv =
        reinterpret_cast<float4*>(out + (size_t)s * RULES);
    const float4* __restrict__ eBv = reinterpret_cast<const float4*>(eB);

    const int base = slice * VECS_PER_SLICE;
    #pragma unroll
    for (int k = 0; k < VECS_PER_SLICE / THREADS; ++k) {   // 16 iterations
        const int i = base + k * THREADS + tid;
        const float  a = eA[i >> 6];       // warp-uniform broadcast
        const float4 b = eBv[i & 63];      // consecutive, conflict-free
        float4 o;
        o.x = a * b.x;
        o.y = a * b.y;
        o.z = a * b.z;
        o.w = a * b.w;
        __stcs(outv + i, o);               // streaming: evict-first in L2
    }
}

extern "C" void kernel_launch(void* const* d_in, const int* in_sizes, int n_in,
                              void* d_out, int out_size)
{
    const float* x      = (const float*)d_in[0];  // model_input [512,8]
    const float* center = (const float*)d_in[1];  // [4,8]
    const float* spread = (const float*)d_in[2];  // [4,8]
    // d_in[3] = fs_ind — deterministic base-4 digit table, decoded in-kernel.
    (void)in_sizes; (void)n_in; (void)out_size;

    float* out = (float*)d_out;                   // [512, 65536] f32

    antecedent_kernel<<<NUM_SAM * SLICES, THREADS>>>(x, center, spread, out);
}